// round 12
// baseline (speedup 1.0000x reference)
#include <cuda_runtime.h>
#include <cuda_fp16.h>
#include <math.h>
#include <stdint.h>

#define BB   256
#define EMB  512
#define CLS  20000
#define NTL  157              // N tiles

#define MT   128
#define NT   128
#define KC   64
#define NCH  (EMB / KC)       // 8 k-chunks
#define STG  32768            // stage bytes: A 16K | B 16K

// ---------------- device scratch ----------------
__device__ __align__(16) __half g_Bh[(size_t)EMB * CLS];   // raw W, fp16
__device__ __align__(16) __half g_Ah[2 * BB * EMB];        // [emb; Wy_norm] fp16
__device__ float g_n2p[8 * CLS];
__device__ float g_inv[CLS];
__device__ float g_xlen[BB];
__device__ float g_pmax[BB * NTL];
__device__ float g_psum[BB * NTL];
__device__ int   g_pbi [BB * NTL];
__device__ float g_inter_sum;
__device__ float g_row_ce[BB];
__device__ int   g_row_correct[BB];

// ---------------- PTX helpers ----------------
__device__ __forceinline__ uint32_t s2u(const void* p) {
    return (uint32_t)__cvta_generic_to_shared(p);
}
__device__ __forceinline__ void cp_async16(uint32_t dst, const void* src, int szbytes) {
    asm volatile("cp.async.cg.shared.global [%0], [%1], 16, %2;"
                 :: "r"(dst), "l"(src), "r"(szbytes));
}
#define CP_COMMIT() asm volatile("cp.async.commit_group;" ::: "memory")
#define CP_WAIT(n)  asm volatile("cp.async.wait_group %0;" :: "n"(n) : "memory")

__device__ __forceinline__ void ldm_x4(uint32_t* r, uint32_t addr) {
    asm volatile("ldmatrix.sync.aligned.m8n8.x4.shared.b16 {%0,%1,%2,%3}, [%4];"
                 : "=r"(r[0]), "=r"(r[1]), "=r"(r[2]), "=r"(r[3]) : "r"(addr));
}
__device__ __forceinline__ void ldm_x4_t(uint32_t* r, uint32_t addr) {
    asm volatile("ldmatrix.sync.aligned.m8n8.x4.trans.shared.b16 {%0,%1,%2,%3}, [%4];"
                 : "=r"(r[0]), "=r"(r[1]), "=r"(r[2]), "=r"(r[3]) : "r"(addr));
}
__device__ __forceinline__ void mma16816(float* c, const uint32_t* a,
                                         uint32_t b0, uint32_t b1) {
    asm volatile("mma.sync.aligned.m16n8k16.row.col.f32.f16.f16.f32 "
                 "{%0,%1,%2,%3}, {%4,%5,%6,%7}, {%8,%9}, {%0,%1,%2,%3};"
                 : "+f"(c[0]), "+f"(c[1]), "+f"(c[2]), "+f"(c[3])
                 : "r"(a[0]), "r"(a[1]), "r"(a[2]), "r"(a[3]), "r"(b0), "r"(b1));
}

// ---------------- fused: W cast fp16 + column-norm partials (single 41MB pass) ----------------
__global__ void k_wprep(const float* __restrict__ W) {
    int j = blockIdx.x * blockDim.x + threadIdx.x;
    if (j >= CLS) return;
    int i0 = blockIdx.y * 64;
    float s = 0.0f;
#pragma unroll 8
    for (int i = 0; i < 64; i++) {
        size_t o = (size_t)(i0 + i) * CLS + j;
        float v = W[o];
        s += v * v;
        g_Bh[o] = __float2half_rn(v);
    }
    g_n2p[blockIdx.y * CLS + j] = s;
}

__global__ void k_nred() {
    int j = blockIdx.x * blockDim.x + threadIdx.x;
    if (blockIdx.x == 0 && threadIdx.x == 0) g_inter_sum = 0.0f;
    if (j >= CLS) return;
    float s = 0.0f;
#pragma unroll
    for (int p = 0; p < 8; p++) s += g_n2p[p * CLS + j];
    g_inv[j] = rsqrtf(s);
}

// 512 blocks: b<BB: emb fp16 + xlen; else Wy = W[:,t]*inv[t] fp16
__global__ void k_prep(const float* __restrict__ emb,
                       const float* __restrict__ W,
                       const int* __restrict__ y) {
    int b = blockIdx.x;
    int tid = threadIdx.x;   // 128
    if (b < BB) {
        float s = 0.0f;
        for (int k = tid; k < EMB; k += 128) {
            float v = emb[b * EMB + k];
            s += v * v;
            g_Ah[b * EMB + k] = __float2half_rn(v);
        }
        __shared__ float sm[128];
        sm[tid] = s;
        __syncthreads();
        for (int o = 64; o > 0; o >>= 1) {
            if (tid < o) sm[tid] += sm[tid + o];
            __syncthreads();
        }
        if (tid == 0) g_xlen[b] = sqrtf(sm[0]);
    } else {
        int t = y[b - BB];
        float inv = g_inv[t];
        for (int k = tid; k < EMB; k += 128)
            g_Ah[b * EMB + k] = __float2half_rn(W[(size_t)k * CLS + t] * inv);
    }
}

// ---------------- fp16 GEMM: 256 thr, 8 warps, 3-stage ring, frag double-buffer ----------------
__global__ __launch_bounds__(256, 2) void k_gemm(const int* __restrict__ y,
                                                 float* __restrict__ logits) {
    extern __shared__ __align__(16) char dsm[];
    __shared__ float sInv[128];
    __shared__ float spm[256];
    __shared__ float sse[256];
    __shared__ int   sbx[256];
    uint32_t sb = s2u(dsm);

    int tid  = threadIdx.x;
    int wid  = tid >> 5, lane = tid & 31;
    int wm   = wid & 3, wn = wid >> 2;    // warp tile 32 (M) x 64 (N)
    int bm   = blockIdx.x, bn = blockIdx.y;
    int rowBase = bm * MT, colBase = bn * NT;

    if (tid < 128) {
        int j = colBase + tid;
        sInv[tid] = (j < CLS) ? g_inv[j] : 1.0f;
    }

    float acc[2][8][4];
#pragma unroll
    for (int mi = 0; mi < 2; mi++)
#pragma unroll
        for (int ni = 0; ni < 8; ni++)
#pragma unroll
            for (int k = 0; k < 4; k++) acc[mi][ni][k] = 0.0f;

    auto load_tiles = [&](int kc, int s) {
        uint32_t base = sb + s * STG;
#pragma unroll
        for (int i = 0; i < 4; i++) {
            int id = i * 256 + tid;
            int r = id >> 3, c8 = id & 7;
            uint32_t soff = (uint32_t)(r * 128 + ((c8 ^ (r & 7)) << 4));
            cp_async16(base + soff, g_Ah + (size_t)(rowBase + r) * EMB + kc + c8 * 8, 16);
        }
#pragma unroll
        for (int i = 0; i < 4; i++) {
            int id = i * 256 + tid;
            int r = id >> 4, c16 = id & 15;
            int col = colBase + c16 * 8;
            int ok = (col < CLS) ? 16 : 0;
            uint32_t soff = (uint32_t)(r * 256 + ((c16 ^ (r & 7)) << 4));
            cp_async16(base + 16384 + soff,
                       g_Bh + (size_t)(kc + r) * CLS + (ok ? col : colBase), ok);
        }
    };

    load_tiles(0, 0); CP_COMMIT();
    load_tiles(KC, 1); CP_COMMIT();

    int ln15 = lane & 15, half = lane >> 4;

    // fragment double buffers
    uint32_t ah[2][2][4], bf[2][4][4];

    for (int ch = 0; ch < NCH; ch++) {
        if (ch + 1 < NCH) { CP_WAIT(1); } else { CP_WAIT(0); }
        __syncthreads();                       // single barrier per chunk (3-stage safe)
        uint32_t base = sb + (ch % 3) * STG;

        // prefetch frags for ks=0 into buffer 0
#pragma unroll
        for (int mi = 0; mi < 2; mi++) {
            int r = wm * 32 + mi * 16 + ln15;
            ldm_x4(ah[0][mi], base + (uint32_t)(r * 128 + ((half ^ (r & 7)) << 4)));
        }
#pragma unroll
        for (int nb = 0; nb < 4; nb++) {
            int r = ln15;
            int c16 = wn * 8 + nb * 2 + half;
            ldm_x4_t(bf[0][nb], base + 16384 + (uint32_t)(r * 256 + ((c16 ^ (r & 7)) << 4)));
        }

        if (ch + 2 < NCH) { load_tiles((ch + 2) * KC, (ch + 2) % 3); CP_COMMIT(); }

#pragma unroll
        for (int ks = 0; ks < 4; ks++) {
            int pb = ks & 1;
            if (ks < 3) {
                int nks = ks + 1;
#pragma unroll
                for (int mi = 0; mi < 2; mi++) {
                    int r = wm * 32 + mi * 16 + ln15;
                    int c8 = nks * 2 + half;
                    ldm_x4(ah[pb ^ 1][mi],
                           base + (uint32_t)(r * 128 + ((c8 ^ (r & 7)) << 4)));
                }
#pragma unroll
                for (int nb = 0; nb < 4; nb++) {
                    int r = nks * 16 + ln15;
                    int c16 = wn * 8 + nb * 2 + half;
                    ldm_x4_t(bf[pb ^ 1][nb],
                             base + 16384 + (uint32_t)(r * 256 + ((c16 ^ (r & 7)) << 4)));
                }
            }
#pragma unroll
            for (int mi = 0; mi < 2; mi++)
#pragma unroll
                for (int ni = 0; ni < 8; ni++)
                    mma16816(acc[mi][ni], ah[pb][mi],
                             bf[pb][ni >> 1][(ni & 1) * 2], bf[pb][ni >> 1][(ni & 1) * 2 + 1]);
        }
    }
    __syncthreads();

    // ---------------- epilogue (normalization applied here: cos_raw = acc * inv[j]) ----------------
    if (bm < 2) {
        float* epi = (float*)dsm;   // [128][129] raw acc
#pragma unroll
        for (int mi = 0; mi < 2; mi++)
#pragma unroll
            for (int ni = 0; ni < 8; ni++)
#pragma unroll
                for (int k = 0; k < 4; k++) {
                    int row = wm * 32 + mi * 16 + (k >> 1) * 8 + (lane >> 2);
                    int col = wn * 64 + ni * 8 + (lane & 3) * 2 + (k & 1);
                    epi[row * 129 + col] = acc[mi][ni][k];
                }
        __syncthreads();
        // coalesced logits store
        {
            int r0 = tid >> 7, c0 = tid & 127;
            int j = colBase + c0;
            if (j < CLS) {
                float inv = sInv[c0];
#pragma unroll 8
                for (int rr = 0; rr < 64; rr++) {
                    int mm = rr * 2 + r0;
                    int b = rowBase + mm;
                    float xl = g_xlen[b];
                    float v = epi[mm * 129 + c0] * inv;
                    float cv = fminf(fmaxf(v / xl, -1.0f), 1.0f);
                    logits[(size_t)b * CLS + j] = cv * xl;
                }
            }
        }
        // per-(row, 64-col-half) softmax/argmax partials
        {
            int row = tid & 127, q = tid >> 7;
            float xl = g_xlen[rowBase + row];
            float bv = -3.0e38f, se = 0.0f;
            int bi = 0x7fffffff;
#pragma unroll 8
            for (int c = 0; c < 64; c++) {
                int lc = q * 64 + c;
                int j = colBase + lc;
                if (j < CLS) {
                    float v = epi[row * 129 + lc] * sInv[lc];
                    float cv = fminf(fmaxf(v / xl, -1.0f), 1.0f) * xl;
                    if (cv > bv) { bv = cv; bi = j; }
                }
            }
#pragma unroll 8
            for (int c = 0; c < 64; c++) {
                int lc = q * 64 + c;
                int j = colBase + lc;
                if (j < CLS) {
                    float v = epi[row * 129 + lc] * sInv[lc];
                    float cv = fminf(fmaxf(v / xl, -1.0f), 1.0f) * xl;
                    se += __expf(cv - bv);
                }
            }
            spm[q * 128 + row] = bv;
            sse[q * 128 + row] = se;
            sbx[q * 128 + row] = bi;
        }
        __syncthreads();
        if (tid < 128) {
            float M = -3.0e38f, sum = 0.0f;
            int bi = 0x7fffffff;
#pragma unroll
            for (int q = 0; q < 2; q++) {
                float m = spm[q * 128 + tid];
                if (m > M) { M = m; bi = sbx[q * 128 + tid]; }
            }
#pragma unroll
            for (int q = 0; q < 2; q++)
                sum += sse[q * 128 + tid] * __expf(spm[q * 128 + tid] - M);
            int b = rowBase + tid;
            g_pmax[b * NTL + bn] = M;
            g_psum[b * NTL + bn] = sum;
            g_pbi [b * NTL + bn] = bi;
        }
    } else {
        float il = 0.0f;
#pragma unroll
        for (int mi = 0; mi < 2; mi++) {
#pragma unroll
            for (int k2 = 0; k2 < 2; k2++) {
                int row = wm * 32 + mi * 16 + k2 * 8 + (lane >> 2);
                int b = rowBase + row - BB;
                int t = y[b];
#pragma unroll
                for (int ni = 0; ni < 8; ni++)
#pragma unroll
                    for (int p = 0; p < 2; p++) {
                        int lc = wn * 64 + ni * 8 + (lane & 3) * 2 + p;
                        int j = colBase + lc;
                        if (j < CLS && j != t) {
                            float c = acc[mi][ni][k2 * 2 + p] * sInv[lc];
                            float d2 = fmaxf(2.0f - 2.0f * c, 0.0f);
                            il += 1.0f / d2;
                        }
                    }
            }
        }
#pragma unroll
        for (int o = 16; o > 0; o >>= 1)
            il += __shfl_down_sync(0xffffffffu, il, o);
        if (lane == 0) atomicAdd(&g_inter_sum, il);
    }
}

// ---------------- per-row combine: 157 partials + margin target ----------------
__global__ __launch_bounds__(256) void k_rows(const float* __restrict__ logits,
                                              const int* __restrict__ y) {
    int b = blockIdx.x;
    int tid = threadIdx.x;
    __shared__ float smx[256];
    __shared__ float ssm[256];
    __shared__ int   sbi[256];
    __shared__ float sM, sOut;

    float m = -3.0e38f, s = 0.0f;
    int idx = 0x7fffffff;
    if (tid < NTL) {
        m = g_pmax[b * NTL + tid];
        s = g_psum[b * NTL + tid];
        idx = g_pbi[b * NTL + tid];
    }
    smx[tid] = m; sbi[tid] = idx;
    __syncthreads();
    for (int o = 128; o > 0; o >>= 1) {
        if (tid < o) {
            float v2 = smx[tid + o]; int i2 = sbi[tid + o];
            if (v2 > smx[tid] || (v2 == smx[tid] && i2 < sbi[tid])) {
                smx[tid] = v2; sbi[tid] = i2;
            }
        }
        __syncthreads();
    }
    float M0 = smx[0];
    int amax = sbi[0];
    int tgt = y[b];

    if (tid == 0) {
        float xl = g_xlen[b];
        float cs_t = logits[(size_t)b * CLS + tgt];
        float ct = cs_t / xl;
        float c2 = ct * ct;
        float cosm = 8.0f * c2 * c2 - 8.0f * c2 + 1.0f;
        const float PI_F = 3.14159265f;
        float theta = acosf(ct);
        float kk = floorf(4.0f * theta / PI_F);
        float sign = 1.0f - 2.0f * fmodf(kk, 2.0f);
        float phi = sign * cosm - 2.0f * kk;
        const float LAMB = 1500.0f / 1.1f;
        const float FCO = 1.0f / (1.0f + LAMB);
        float out_t = cs_t + FCO * (phi * xl - cs_t);
        sOut = out_t;
        sM = fmaxf(M0, out_t);
    }
    __syncthreads();
    float M = sM;
    ssm[tid] = s * __expf(m - M);
    __syncthreads();
    for (int o = 128; o > 0; o >>= 1) {
        if (tid < o) ssm[tid] += ssm[tid + o];
        __syncthreads();
    }
    if (tid == 0) {
        float out_t = sOut;
        float cs_t = logits[(size_t)b * CLS + tgt];
        float sum = ssm[0] + __expf(out_t - M) - __expf(cs_t - M);
        float lse = logf(sum);
        g_row_ce[b] = -(out_t - M - lse);
        g_row_correct[b] = (amax == tgt) ? 1 : 0;
    }
}

__global__ __launch_bounds__(256) void k_final(float* __restrict__ out) {
    __shared__ float s[256];
    __shared__ int   c[256];
    int tid = threadIdx.x;
    s[tid] = g_row_ce[tid];
    c[tid] = g_row_correct[tid];
    __syncthreads();
    for (int o = 128; o > 0; o >>= 1) {
        if (tid < o) { s[tid] += s[tid + o]; c[tid] += c[tid + o]; }
        __syncthreads();
    }
    if (tid == 0) {
        float ce = s[0] / (float)BB;
        float inter = g_inter_sum / ((float)BB * (float)(CLS - 1));
        out[0] = ce + 0.01f * inter;
        out[1 + BB * CLS] = (float)c[0] / (float)BB;
        out[2 + BB * CLS] = inter;
    }
}

// ---------------- launch ----------------
extern "C" void kernel_launch(void* const* d_in, const int* in_sizes, int n_in,
                              void* d_out, int out_size) {
    const float* emb = (const float*)d_in[0];
    const int*   y   = (const int*)d_in[1];
    const float* W   = (const float*)d_in[2];
    float* out = (float*)d_out;
    float* logits = out + 1;

    const int DSM = 3 * STG;   // 96KB: 3-stage ring; 128x129 f32 epi tile (66KB) overlays
    cudaFuncSetAttribute(k_gemm, cudaFuncAttributeMaxDynamicSharedMemorySize, DSM);

    dim3 gwp((CLS + 255) / 256, 8);
    k_wprep<<<gwp, 256>>>(W);
    k_nred<<<(CLS + 255) / 256, 256>>>();
    k_prep<<<2 * BB, 128>>>(emb, W, y);
    dim3 grid((2 * BB) / MT, NTL);   // 4 x 157
    k_gemm<<<grid, 256, DSM>>>(y, logits);
    k_rows<<<BB, 256>>>(logits, y);
    k_final<<<1, 256>>>(out);
}

// round 14
// speedup vs baseline: 1.1280x; 1.1280x over previous
#include <cuda_runtime.h>
#include <cuda_fp16.h>
#include <math.h>
#include <stdint.h>

#define BB   256
#define EMB  512
#define CLS  20000
#define NT   64
#define NTL  313              // ceil(CLS/NT)
#define MT   128
#define KC   64
#define NCH  (EMB / KC)       // 8 k-chunks
#define STG  24576            // stage bytes: A 16K | B 8K

// ---------------- device scratch ----------------
__device__ __align__(16) __half g_Bh[(size_t)EMB * CLS];   // raw W, fp16
__device__ __align__(16) __half g_Ah[2 * BB * EMB];        // [emb; Wy_norm] fp16
__device__ float g_n2p[8 * CLS];
__device__ float g_inv[CLS];
__device__ float g_xlen[BB];
__device__ float g_pmax[BB * NTL];
__device__ float g_psum[BB * NTL];
__device__ int   g_pbi [BB * NTL];
__device__ float g_inter_sum;
__device__ float g_row_ce[BB];
__device__ int   g_row_correct[BB];

// ---------------- PTX helpers ----------------
__device__ __forceinline__ uint32_t s2u(const void* p) {
    return (uint32_t)__cvta_generic_to_shared(p);
}
__device__ __forceinline__ void cp_async16(uint32_t dst, const void* src, int szbytes) {
    asm volatile("cp.async.cg.shared.global [%0], [%1], 16, %2;"
                 :: "r"(dst), "l"(src), "r"(szbytes));
}
#define CP_COMMIT() asm volatile("cp.async.commit_group;" ::: "memory")
#define CP_WAIT(n)  asm volatile("cp.async.wait_group %0;" :: "n"(n) : "memory")

__device__ __forceinline__ void ldm_x4(uint32_t* r, uint32_t addr) {
    asm volatile("ldmatrix.sync.aligned.m8n8.x4.shared.b16 {%0,%1,%2,%3}, [%4];"
                 : "=r"(r[0]), "=r"(r[1]), "=r"(r[2]), "=r"(r[3]) : "r"(addr));
}
__device__ __forceinline__ void ldm_x4_t(uint32_t* r, uint32_t addr) {
    asm volatile("ldmatrix.sync.aligned.m8n8.x4.trans.shared.b16 {%0,%1,%2,%3}, [%4];"
                 : "=r"(r[0]), "=r"(r[1]), "=r"(r[2]), "=r"(r[3]) : "r"(addr));
}
__device__ __forceinline__ void mma16816(float* c, const uint32_t* a,
                                         uint32_t b0, uint32_t b1) {
    asm volatile("mma.sync.aligned.m16n8k16.row.col.f32.f16.f16.f32 "
                 "{%0,%1,%2,%3}, {%4,%5,%6,%7}, {%8,%9}, {%0,%1,%2,%3};"
                 : "+f"(c[0]), "+f"(c[1]), "+f"(c[2]), "+f"(c[3])
                 : "r"(a[0]), "r"(a[1]), "r"(a[2]), "r"(a[3]), "r"(b0), "r"(b1));
}

// ---------------- fused: W cast fp16 + column-norm partials ----------------
__global__ void k_wprep(const float* __restrict__ W) {
    int j = blockIdx.x * blockDim.x + threadIdx.x;
    if (j >= CLS) return;
    int i0 = blockIdx.y * 64;
    float s = 0.0f;
#pragma unroll 8
    for (int i = 0; i < 64; i++) {
        size_t o = (size_t)(i0 + i) * CLS + j;
        float v = W[o];
        s += v * v;
        g_Bh[o] = __float2half_rn(v);
    }
    g_n2p[blockIdx.y * CLS + j] = s;
}

__global__ void k_nred() {
    int j = blockIdx.x * blockDim.x + threadIdx.x;
    if (blockIdx.x == 0 && threadIdx.x == 0) g_inter_sum = 0.0f;
    if (j >= CLS) return;
    float s = 0.0f;
#pragma unroll
    for (int p = 0; p < 8; p++) s += g_n2p[p * CLS + j];
    g_inv[j] = rsqrtf(s);
}

__global__ void k_prep(const float* __restrict__ emb,
                       const float* __restrict__ W,
                       const int* __restrict__ y) {
    int b = blockIdx.x;
    int tid = threadIdx.x;   // 128
    if (b < BB) {
        float s = 0.0f;
        for (int k = tid; k < EMB; k += 128) {
            float v = emb[b * EMB + k];
            s += v * v;
            g_Ah[b * EMB + k] = __float2half_rn(v);
        }
        __shared__ float sm[128];
        sm[tid] = s;
        __syncthreads();
        for (int o = 64; o > 0; o >>= 1) {
            if (tid < o) sm[tid] += sm[tid + o];
            __syncthreads();
        }
        if (tid == 0) g_xlen[b] = sqrtf(sm[0]);
    } else {
        int t = y[b - BB];
        float inv = g_inv[t];
        for (int k = tid; k < EMB; k += 128)
            g_Ah[b * EMB + k] = __float2half_rn(W[(size_t)k * CLS + t] * inv);
    }
}

// ---------------- fp16 GEMM: 128x64 tile, 8 warps (32x32), 3 CTAs/SM ----------------
__global__ __launch_bounds__(256, 3) void k_gemm(const int* __restrict__ y,
                                                 float* __restrict__ logits) {
    extern __shared__ __align__(16) char dsm[];
    __shared__ float sInv[64];
    __shared__ float spm[256];
    __shared__ float sse[256];
    __shared__ int   sbx[256];
    uint32_t sb = s2u(dsm);

    int tid  = threadIdx.x;
    int wid  = tid >> 5, lane = tid & 31;
    int wm   = wid & 3, wn = wid >> 2;    // warp tile 32 (M) x 32 (N)
    int bm   = blockIdx.x, bn = blockIdx.y;
    int rowBase = bm * MT, colBase = bn * NT;

    if (tid < 64) {
        int j = colBase + tid;
        sInv[tid] = (j < CLS) ? g_inv[j] : 1.0f;
    }

    float acc[2][4][4];
#pragma unroll
    for (int mi = 0; mi < 2; mi++)
#pragma unroll
        for (int ni = 0; ni < 4; ni++)
#pragma unroll
            for (int k = 0; k < 4; k++) acc[mi][ni][k] = 0.0f;

    // A: 128x64 fp16 (128B rows, swz c8^(r&7)); B: 64x64 fp16 (128B rows, same swz)
    auto load_tiles = [&](int kc, int s) {
        uint32_t base = sb + s * STG;
#pragma unroll
        for (int i = 0; i < 4; i++) {           // A: 1024 16B chunks
            int id = i * 256 + tid;
            int r = id >> 3, c8 = id & 7;
            uint32_t soff = (uint32_t)(r * 128 + ((c8 ^ (r & 7)) << 4));
            cp_async16(base + soff, g_Ah + (size_t)(rowBase + r) * EMB + kc + c8 * 8, 16);
        }
#pragma unroll
        for (int i = 0; i < 2; i++) {           // B: 512 16B chunks
            int id = i * 256 + tid;
            int r = id >> 3, c8 = id & 7;
            int col = colBase + c8 * 8;
            int ok = (col < CLS) ? 16 : 0;
            uint32_t soff = (uint32_t)(r * 128 + ((c8 ^ (r & 7)) << 4));
            cp_async16(base + 16384 + soff,
                       g_Bh + (size_t)(kc + r) * CLS + (ok ? col : colBase), ok);
        }
    };

    load_tiles(0, 0); CP_COMMIT();
    load_tiles(KC, 1); CP_COMMIT();

    int ln15 = lane & 15, half = lane >> 4;

    for (int ch = 0; ch < NCH; ch++) {
        if (ch + 1 < NCH) { CP_WAIT(1); } else { CP_WAIT(0); }
        __syncthreads();
        uint32_t base = sb + (ch & 1) * STG;
#pragma unroll
        for (int ks = 0; ks < 4; ks++) {
            uint32_t ah[2][4], bf[2][4];
#pragma unroll
            for (int mi = 0; mi < 2; mi++) {
                int r = wm * 32 + mi * 16 + ln15;
                int c8 = ks * 2 + half;
                ldm_x4(ah[mi], base + (uint32_t)(r * 128 + ((c8 ^ (r & 7)) << 4)));
            }
#pragma unroll
            for (int nb = 0; nb < 2; nb++) {
                int r = ks * 16 + ln15;
                int c8 = wn * 4 + nb * 2 + half;
                ldm_x4_t(bf[nb], base + 16384 + (uint32_t)(r * 128 + ((c8 ^ (r & 7)) << 4)));
            }
#pragma unroll
            for (int mi = 0; mi < 2; mi++)
#pragma unroll
                for (int ni = 0; ni < 4; ni++)
                    mma16816(acc[mi][ni], ah[mi],
                             bf[ni >> 1][(ni & 1) * 2], bf[ni >> 1][(ni & 1) * 2 + 1]);
        }
        __syncthreads();
        if (ch + 2 < NCH) { load_tiles((ch + 2) * KC, ch & 1); CP_COMMIT(); }
    }

    // ---------------- epilogue ----------------
    if (bm < 2) {
        float* epi = (float*)dsm;   // [128][65]
#pragma unroll
        for (int mi = 0; mi < 2; mi++)
#pragma unroll
            for (int ni = 0; ni < 4; ni++)
#pragma unroll
                for (int k = 0; k < 4; k++) {
                    int row = wm * 32 + mi * 16 + (k >> 1) * 8 + (lane >> 2);
                    int col = wn * 32 + ni * 8 + (lane & 3) * 2 + (k & 1);
                    epi[row * 65 + col] = acc[mi][ni][k];
                }
        __syncthreads();
        // coalesced logits store
        {
            int r0 = tid >> 6, c0 = tid & 63;   // r0 0..3
            int j = colBase + c0;
            if (j < CLS) {
                float inv = sInv[c0];
#pragma unroll 8
                for (int rr = 0; rr < 32; rr++) {
                    int mm = rr * 4 + r0;
                    int b = rowBase + mm;
                    float xl = g_xlen[b];
                    float v = epi[mm * 65 + c0] * inv;
                    float cv = fminf(fmaxf(v / xl, -1.0f), 1.0f);
                    logits[(size_t)b * CLS + j] = cv * xl;
                }
            }
        }
        // per-(row, 32-col-half) softmax/argmax partials
        {
            int row = tid & 127, q = tid >> 7;
            float xl = g_xlen[rowBase + row];
            float bv = -3.0e38f, se = 0.0f;
            int bi = 0x7fffffff;
#pragma unroll 8
            for (int c = 0; c < 32; c++) {
                int lc = q * 32 + c;
                int j = colBase + lc;
                if (j < CLS) {
                    float v = epi[row * 65 + lc] * sInv[lc];
                    float cv = fminf(fmaxf(v / xl, -1.0f), 1.0f) * xl;
                    if (cv > bv) { bv = cv; bi = j; }
                }
            }
#pragma unroll 8
            for (int c = 0; c < 32; c++) {
                int lc = q * 32 + c;
                int j = colBase + lc;
                if (j < CLS) {
                    float v = epi[row * 65 + lc] * sInv[lc];
                    float cv = fminf(fmaxf(v / xl, -1.0f), 1.0f) * xl;
                    se += __expf(cv - bv);
                }
            }
            spm[q * 128 + row] = bv;
            sse[q * 128 + row] = se;
            sbx[q * 128 + row] = bi;
        }
        __syncthreads();
        if (tid < 128) {
            float m0 = spm[tid], m1 = spm[128 + tid];
            float M = fmaxf(m0, m1);
            float sum = sse[tid] * __expf(m0 - M) + sse[128 + tid] * __expf(m1 - M);
            int bi = (m1 > m0) ? sbx[128 + tid] : sbx[tid];
            int b = rowBase + tid;
            g_pmax[b * NTL + bn] = M;
            g_psum[b * NTL + bn] = sum;
            g_pbi [b * NTL + bn] = bi;
        }
    } else {
        float il = 0.0f;
#pragma unroll
        for (int mi = 0; mi < 2; mi++) {
#pragma unroll
            for (int k2 = 0; k2 < 2; k2++) {
                int row = wm * 32 + mi * 16 + k2 * 8 + (lane >> 2);
                int b = rowBase + row - BB;
                int t = y[b];
#pragma unroll
                for (int ni = 0; ni < 4; ni++)
#pragma unroll
                    for (int p = 0; p < 2; p++) {
                        int lc = wn * 32 + ni * 8 + (lane & 3) * 2 + p;
                        int j = colBase + lc;
                        if (j < CLS && j != t) {
                            float c = acc[mi][ni][k2 * 2 + p] * sInv[lc];
                            float d2 = fmaxf(2.0f - 2.0f * c, 0.0f);
                            il += 1.0f / d2;
                        }
                    }
            }
        }
#pragma unroll
        for (int o = 16; o > 0; o >>= 1)
            il += __shfl_down_sync(0xffffffffu, il, o);
        if (lane == 0) atomicAdd(&g_inter_sum, il);
    }
}

// ---------------- per-row combine: 313 partials + margin target ----------------
__global__ __launch_bounds__(256) void k_rows(const float* __restrict__ logits,
                                              const int* __restrict__ y) {
    int b = blockIdx.x;
    int tid = threadIdx.x;
    __shared__ float smx[256];
    __shared__ float ssm[256];
    __shared__ int   sbi[256];

    // online combine over strided partials
    float m = -3.0e38f, s = 0.0f;
    int idx = 0x7fffffff;
    for (int t = tid; t < NTL; t += 256) {
        float pm = g_pmax[b * NTL + t];
        float ps = g_psum[b * NTL + t];
        int   pi = g_pbi [b * NTL + t];
        if (pm > m) {
            s = s * __expf(m - pm) + ps;
            m = pm; idx = pi;
        } else {
            s += ps * __expf(pm - m);
            if (pm == m && pi < idx) idx = pi;
        }
    }
    smx[tid] = m; ssm[tid] = s; sbi[tid] = idx;
    __syncthreads();
    for (int o = 128; o > 0; o >>= 1) {
        if (tid < o) {
            float m2 = smx[tid + o], s2 = ssm[tid + o];
            int i2 = sbi[tid + o];
            float m1 = smx[tid];
            if (m2 > m1) {
                ssm[tid] = ssm[tid] * __expf(m1 - m2) + s2;
                smx[tid] = m2; sbi[tid] = i2;
            } else {
                ssm[tid] += s2 * __expf(m2 - m1);
                if (m2 == m1 && i2 < sbi[tid]) sbi[tid] = i2;
            }
        }
        __syncthreads();
    }
    float M0 = smx[0], S0 = ssm[0];
    int amax = sbi[0];
    int tgt = y[b];

    if (tid == 0) {
        float xl = g_xlen[b];
        float cs_t = logits[(size_t)b * CLS + tgt];
        float ct = cs_t / xl;
        float c2 = ct * ct;
        float cosm = 8.0f * c2 * c2 - 8.0f * c2 + 1.0f;
        const float PI_F = 3.14159265f;
        float theta = acosf(ct);
        float kk = floorf(4.0f * theta / PI_F);
        float sign = 1.0f - 2.0f * fmodf(kk, 2.0f);
        float phi = sign * cosm - 2.0f * kk;
        const float LAMB = 1500.0f / 1.1f;
        const float FCO = 1.0f / (1.0f + LAMB);
        float out_t = cs_t + FCO * (phi * xl - cs_t);
        float M = fmaxf(M0, out_t);
        float sum = S0 * __expf(M0 - M) + __expf(out_t - M) - __expf(cs_t - M);
        float lse = logf(sum);
        g_row_ce[b] = -(out_t - M - lse);
        g_row_correct[b] = (amax == tgt) ? 1 : 0;
    }
}

__global__ __launch_bounds__(256) void k_final(float* __restrict__ out) {
    __shared__ float s[256];
    __shared__ int   c[256];
    int tid = threadIdx.x;
    s[tid] = g_row_ce[tid];
    c[tid] = g_row_correct[tid];
    __syncthreads();
    for (int o = 128; o > 0; o >>= 1) {
        if (tid < o) { s[tid] += s[tid + o]; c[tid] += c[tid + o]; }
        __syncthreads();
    }
    if (tid == 0) {
        float ce = s[0] / (float)BB;
        float inter = g_inter_sum / ((float)BB * (float)(CLS - 1));
        out[0] = ce + 0.01f * inter;
        out[1 + BB * CLS] = (float)c[0] / (float)BB;
        out[2 + BB * CLS] = inter;
    }
}

// ---------------- launch ----------------
extern "C" void kernel_launch(void* const* d_in, const int* in_sizes, int n_in,
                              void* d_out, int out_size) {
    const float* emb = (const float*)d_in[0];
    const int*   y   = (const int*)d_in[1];
    const float* W   = (const float*)d_in[2];
    float* out = (float*)d_out;
    float* logits = out + 1;

    const int DSM = 2 * STG;   // 48KB: 2-stage; 128x65 f32 epi tile (33KB) overlays
    cudaFuncSetAttribute(k_gemm, cudaFuncAttributeMaxDynamicSharedMemorySize, DSM);

    dim3 gwp((CLS + 255) / 256, 8);
    k_wprep<<<gwp, 256>>>(W);
    k_nred<<<(CLS + 255) / 256, 256>>>();
    k_prep<<<2 * BB, 128>>>(emb, W, y);
    dim3 grid((2 * BB) / MT, NTL);   // 4 x 313
    k_gemm<<<grid, 256, DSM>>>(y, logits);
    k_rows<<<BB, 256>>>(logits, y);
    k_final<<<1, 256>>>(out);
}